// round 2
// baseline (speedup 1.0000x reference)
#include <cuda_runtime.h>
#include <math.h>

#define BB 4
#define SS 1024
#define DD 512
#define HH 8
#define HD 64
#define NP 1025   // pemb rows (2*512+1)

// ---------------- scratch (device globals; allocation-free) ----------------
__device__ float g_q[BB*HH*SS*HD];              // [b,h,s,d], pre-scaled by 0.125
__device__ float g_k[BB*HH*SS*HD];
__device__ float g_v[BB*HH*SS*HD];
__device__ float g_qp[(size_t)BB*HH*SS*NP];     // [b,h,s, 1025]
__device__ float g_ctx[BB*SS*HH*HD];            // [b,s, h*64+d]

// ============================================================================
// Kernel 1: QKV projection.  C[m,n] = sum_k x[m,k] * W(k,n),
// M=4096, N=1536 (q|k|v), K=512.  Epilogue scatters into head-major q/k/v.
// ============================================================================
__global__ __launch_bounds__(256) void qkv_gemm(const float* __restrict__ x,
                                                const float* __restrict__ Wq,
                                                const float* __restrict__ Wkv) {
    __shared__ float As[16][68];
    __shared__ float Bs[16][68];
    const int m0 = blockIdx.y * 64;
    const int n0 = blockIdx.x * 64;
    const int tid = threadIdx.x;
    const int ty = tid >> 4, tx = tid & 15;

    float acc[4][4] = {};

    for (int k0 = 0; k0 < DD; k0 += 16) {
        // A tile: x rows m0..m0+63, cols k0..k0+15 (store transposed)
        {
            int row = tid >> 2;
            int cg  = (tid & 3) * 4;
            float4 v = *(const float4*)&x[(size_t)(m0 + row) * DD + k0 + cg];
            As[cg + 0][row] = v.x; As[cg + 1][row] = v.y;
            As[cg + 2][row] = v.z; As[cg + 3][row] = v.w;
        }
        // B tile: W rows k0..k0+15, cols n0..n0+63
        {
            int kk = tid >> 4;
            int c  = (tid & 15) * 4;
            int n  = n0 + c;
            float4 v;
            if (n < 512) v = *(const float4*)&Wq[(size_t)(k0 + kk) * 512 + n];
            else         v = *(const float4*)&Wkv[(size_t)(k0 + kk) * 1024 + (n - 512)];
            Bs[kk][c + 0] = v.x; Bs[kk][c + 1] = v.y;
            Bs[kk][c + 2] = v.z; Bs[kk][c + 3] = v.w;
        }
        __syncthreads();
        #pragma unroll
        for (int kk = 0; kk < 16; kk++) {
            float a[4], b[4];
            #pragma unroll
            for (int i = 0; i < 4; i++) a[i] = As[kk][ty * 4 + i];
            #pragma unroll
            for (int j = 0; j < 4; j++) b[j] = Bs[kk][tx * 4 + j];
            #pragma unroll
            for (int i = 0; i < 4; i++)
                #pragma unroll
                for (int j = 0; j < 4; j++) acc[i][j] += a[i] * b[j];
        }
        __syncthreads();
    }

    #pragma unroll
    for (int i = 0; i < 4; i++) {
        int m = m0 + ty * 4 + i;
        int b = m >> 10, s = m & 1023;
        #pragma unroll
        for (int j = 0; j < 4; j++) {
            int n = n0 + tx * 4 + j;
            float val = acc[i][j];
            float* dst; int hcol;
            if (n < 512)        { dst = g_q; hcol = n;        val *= 0.125f; }
            else if (n < 1024)  { dst = g_k; hcol = n - 512;  }
            else                { dst = g_v; hcol = n - 1024; }
            int h = hcol >> 6, d = hcol & 63;
            dst[(((size_t)(b * HH + h) << 10) + s) * HD + d] = val;
        }
    }
}

// ============================================================================
// Kernel 2: QP = q @ pemb^T.  M=32768 ((b,h,s) flat), N=1025, K=64.
// q already scaled by 0.125.
// ============================================================================
__global__ __launch_bounds__(256) void qp_gemm(const float* __restrict__ pemb) {
    __shared__ float As[16][68];
    __shared__ float Bs[16][68];
    const int m0 = blockIdx.y * 64;
    const int n0 = blockIdx.x * 64;
    const int tid = threadIdx.x;
    const int ty = tid >> 4, tx = tid & 15;

    float acc[4][4] = {};

    for (int k0 = 0; k0 < HD; k0 += 16) {
        {
            int row = tid >> 2;
            int cg  = (tid & 3) * 4;
            float4 v = *(const float4*)&g_q[(size_t)(m0 + row) * HD + k0 + cg];
            As[cg + 0][row] = v.x; As[cg + 1][row] = v.y;
            As[cg + 2][row] = v.z; As[cg + 3][row] = v.w;
        }
        {
            // B(k,n) = pemb[n*64 + k]; load pemb row-major, store transposed
            int nl = tid >> 2;           // 0..63
            int kg = (tid & 3) * 4;      // 0,4,8,12
            int n  = n0 + nl;
            float4 v = make_float4(0.f, 0.f, 0.f, 0.f);
            if (n < NP) v = *(const float4*)&pemb[(size_t)n * HD + k0 + kg];
            Bs[kg + 0][nl] = v.x; Bs[kg + 1][nl] = v.y;
            Bs[kg + 2][nl] = v.z; Bs[kg + 3][nl] = v.w;
        }
        __syncthreads();
        #pragma unroll
        for (int kk = 0; kk < 16; kk++) {
            float a[4], b[4];
            #pragma unroll
            for (int i = 0; i < 4; i++) a[i] = As[kk][ty * 4 + i];
            #pragma unroll
            for (int j = 0; j < 4; j++) b[j] = Bs[kk][tx * 4 + j];
            #pragma unroll
            for (int i = 0; i < 4; i++)
                #pragma unroll
                for (int j = 0; j < 4; j++) acc[i][j] += a[i] * b[j];
        }
        __syncthreads();
    }

    #pragma unroll
    for (int i = 0; i < 4; i++) {
        int m = m0 + ty * 4 + i;
        #pragma unroll
        for (int j = 0; j < 4; j++) {
            int n = n0 + tx * 4 + j;
            if (n < NP) g_qp[(size_t)m * NP + n] = acc[i][j];
        }
    }
}

// ============================================================================
// Kernel 3: flash-style attention with positional gather.
// Block = 256 threads. Query tile 64, key tile 32, hd=64.
// Per-row softmax state replicated across the 16-lane tx group.
// ============================================================================
__global__ __launch_bounds__(256) void attn_kernel() {
    const int bh = blockIdx.y;            // 0..31  (b*8+h)
    const int q0 = blockIdx.x * 64;       // query tile start
    const int tid = threadIdx.x;
    const int ty = tid >> 4, tx = tid & 15;

    __shared__ float sQ[64][65];
    __shared__ float sK[32][65];
    __shared__ float sV[32][65];
    __shared__ float sP[64][33];

    // load Q tile [64][64]
    #pragma unroll
    for (int it = 0; it < 4; it++) {
        int row = it * 16 + (tid >> 4);
        int cg  = (tid & 15) * 4;
        float4 v = *(const float4*)&g_q[((size_t)bh * SS + q0 + row) * HD + cg];
        sQ[row][cg + 0] = v.x; sQ[row][cg + 1] = v.y;
        sQ[row][cg + 2] = v.z; sQ[row][cg + 3] = v.w;
    }

    float o[4][4] = {};
    float rmax[4], rsum[4];
    #pragma unroll
    for (int i = 0; i < 4; i++) { rmax[i] = -1e30f; rsum[i] = 0.f; }

    for (int kt = 0; kt < SS / 32; kt++) {
        const int t0 = kt * 32;
        // load K,V tiles [32][64]
        #pragma unroll
        for (int it = 0; it < 2; it++) {
            int row = it * 16 + (tid >> 4);
            int cg  = (tid & 15) * 4;
            size_t base = ((size_t)bh * SS + t0 + row) * HD + cg;
            float4 kv = *(const float4*)&g_k[base];
            sK[row][cg + 0] = kv.x; sK[row][cg + 1] = kv.y;
            sK[row][cg + 2] = kv.z; sK[row][cg + 3] = kv.w;
            float4 vv = *(const float4*)&g_v[base];
            sV[row][cg + 0] = vv.x; sV[row][cg + 1] = vv.y;
            sV[row][cg + 2] = vv.z; sV[row][cg + 3] = vv.w;
        }
        __syncthreads();

        // S tile 64x32: each thread 4 rows x 2 cols
        float sc[4][2] = {};
        #pragma unroll
        for (int d = 0; d < 64; d++) {
            float a[4], b[2];
            #pragma unroll
            for (int i = 0; i < 4; i++) a[i] = sQ[ty * 4 + i][d];
            #pragma unroll
            for (int j = 0; j < 2; j++) b[j] = sK[tx * 2 + j][d];
            #pragma unroll
            for (int i = 0; i < 4; i++)
                #pragma unroll
                for (int j = 0; j < 2; j++) sc[i][j] += a[i] * b[j];
        }
        // add positional bias (gather from qp; already scaled)
        #pragma unroll
        for (int i = 0; i < 4; i++) {
            int s_g = q0 + ty * 4 + i;
            size_t rowbase = ((size_t)bh * SS + s_g) * NP;
            #pragma unroll
            for (int j = 0; j < 2; j++) {
                int t = t0 + tx * 2 + j;
                int dlt = s_g - t;
                dlt = min(512, max(-512, dlt));
                sc[i][j] += g_qp[rowbase + dlt + 512];
            }
        }
        // online softmax per row (16-lane groups share a row)
        #pragma unroll
        for (int i = 0; i < 4; i++) {
            float m = fmaxf(sc[i][0], sc[i][1]);
            #pragma unroll
            for (int off = 8; off > 0; off >>= 1)
                m = fmaxf(m, __shfl_xor_sync(0xffffffffu, m, off));
            float newm = fmaxf(rmax[i], m);
            float corr = __expf(rmax[i] - newm);
            rmax[i] = newm;
            float p0 = __expf(sc[i][0] - newm);
            float p1 = __expf(sc[i][1] - newm);
            float lsum = p0 + p1;
            #pragma unroll
            for (int off = 8; off > 0; off >>= 1)
                lsum += __shfl_xor_sync(0xffffffffu, lsum, off);
            rsum[i] = rsum[i] * corr + lsum;
            sP[ty * 4 + i][tx * 2 + 0] = p0;
            sP[ty * 4 + i][tx * 2 + 1] = p1;
            #pragma unroll
            for (int j = 0; j < 4; j++) o[i][j] *= corr;
        }
        __syncthreads();

        // O += P @ V : each thread 4 rows x 4 hd-cols, c over 32 keys
        #pragma unroll
        for (int c = 0; c < 32; c++) {
            float p[4], v[4];
            #pragma unroll
            for (int i = 0; i < 4; i++) p[i] = sP[ty * 4 + i][c];
            #pragma unroll
            for (int j = 0; j < 4; j++) v[j] = sV[c][tx * 4 + j];
            #pragma unroll
            for (int i = 0; i < 4; i++)
                #pragma unroll
                for (int j = 0; j < 4; j++) o[i][j] += p[i] * v[j];
        }
        __syncthreads();
    }

    // write ctx [b, s, h*64+d]
    const int b = bh >> 3, h = bh & 7;
    #pragma unroll
    for (int i = 0; i < 4; i++) {
        int s = q0 + ty * 4 + i;
        float inv = 1.0f / rsum[i];
        #pragma unroll
        for (int j = 0; j < 4; j++) {
            int d = tx * 4 + j;
            g_ctx[((size_t)(b * SS + s) * (HH * HD)) + h * HD + d] = o[i][j] * inv;
        }
    }
}

// ============================================================================
// Kernel 4: output projection.  out = ctx @ Wout + bout.  M=4096,N=512,K=512.
// ============================================================================
__global__ __launch_bounds__(256) void out_gemm(const float* __restrict__ Wout,
                                                const float* __restrict__ bout,
                                                float* __restrict__ out) {
    __shared__ float As[16][68];
    __shared__ float Bs[16][68];
    const int m0 = blockIdx.y * 64;
    const int n0 = blockIdx.x * 64;
    const int tid = threadIdx.x;
    const int ty = tid >> 4, tx = tid & 15;

    float acc[4][4] = {};

    for (int k0 = 0; k0 < DD; k0 += 16) {
        {
            int row = tid >> 2;
            int cg  = (tid & 3) * 4;
            float4 v = *(const float4*)&g_ctx[(size_t)(m0 + row) * DD + k0 + cg];
            As[cg + 0][row] = v.x; As[cg + 1][row] = v.y;
            As[cg + 2][row] = v.z; As[cg + 3][row] = v.w;
        }
        {
            int kk = tid >> 4;
            int c  = (tid & 15) * 4;
            float4 v = *(const float4*)&Wout[(size_t)(k0 + kk) * DD + n0 + c];
            Bs[kk][c + 0] = v.x; Bs[kk][c + 1] = v.y;
            Bs[kk][c + 2] = v.z; Bs[kk][c + 3] = v.w;
        }
        __syncthreads();
        #pragma unroll
        for (int kk = 0; kk < 16; kk++) {
            float a[4], b[4];
            #pragma unroll
            for (int i = 0; i < 4; i++) a[i] = As[kk][ty * 4 + i];
            #pragma unroll
            for (int j = 0; j < 4; j++) b[j] = Bs[kk][tx * 4 + j];
            #pragma unroll
            for (int i = 0; i < 4; i++)
                #pragma unroll
                for (int j = 0; j < 4; j++) acc[i][j] += a[i] * b[j];
        }
        __syncthreads();
    }

    #pragma unroll
    for (int i = 0; i < 4; i++) {
        int m = m0 + ty * 4 + i;
        #pragma unroll
        for (int j = 0; j < 4; j++) {
            int n = n0 + tx * 4 + j;
            out[(size_t)m * DD + n] = acc[i][j] + bout[n];
        }
    }
}

// ============================================================================
extern "C" void kernel_launch(void* const* d_in, const int* in_sizes, int n_in,
                              void* d_out, int out_size) {
    const float* x    = (const float*)d_in[0];
    // d_in[1] = attn_mask (unused by reference)
    const float* Wq   = (const float*)d_in[2];
    const float* Wkv  = (const float*)d_in[3];
    const float* Wout = (const float*)d_in[4];
    const float* bout = (const float*)d_in[5];
    const float* pemb = (const float*)d_in[6];
    float* out = (float*)d_out;

    // 1) QKV projection (M=4096, N=1536)
    qkv_gemm<<<dim3(1536 / 64, 4096 / 64), 256>>>(x, Wq, Wkv);

    // 2) qp = q @ pemb^T (M=32768, N=1025)
    qp_gemm<<<dim3((NP + 63) / 64, (BB * HH * SS) / 64), 256>>>(pemb);

    // 3) attention (16 q-tiles x 32 (b,h))
    attn_kernel<<<dim3(SS / 64, BB * HH), 256>>>();

    // 4) output projection (M=4096, N=512)
    out_gemm<<<dim3(DD / 64, 4096 / 64), 256>>>(Wout, bout, out);
}

// round 3
// speedup vs baseline: 1.0000x; 1.0000x over previous
#include <cuda_runtime.h>
#include <math.h>

#define BB 4
#define SS 1024
#define DD 512
#define HH 8
#define HD 64
#define NP 1025   // pemb rows (2*512+1)

// ---------------- scratch (device globals; allocation-free) ----------------
__device__ float g_q[BB*HH*SS*HD];              // [b,h,s,d], pre-scaled by 0.125
__device__ float g_k[BB*HH*SS*HD];
__device__ float g_v[BB*HH*SS*HD];
__device__ float g_qp[(size_t)BB*HH*SS*NP];     // [b,h,s, 1025]
__device__ float g_ctx[BB*SS*HH*HD];            // [b,s, h*64+d]

// ============================================================================
// Kernel 1: QKV projection.  C[m,n] = sum_k x[m,k] * W(k,n),
// M=4096, N=1536 (q|k|v), K=512.  Epilogue scatters into head-major q/k/v.
// ============================================================================
__global__ __launch_bounds__(256) void qkv_gemm(const float* __restrict__ x,
                                                const float* __restrict__ Wq,
                                                const float* __restrict__ Wkv) {
    __shared__ float As[16][68];
    __shared__ float Bs[16][68];
    const int m0 = blockIdx.y * 64;
    const int n0 = blockIdx.x * 64;
    const int tid = threadIdx.x;
    const int ty = tid >> 4, tx = tid & 15;

    float acc[4][4] = {};

    for (int k0 = 0; k0 < DD; k0 += 16) {
        // A tile: x rows m0..m0+63, cols k0..k0+15 (store transposed)
        {
            int row = tid >> 2;
            int cg  = (tid & 3) * 4;
            float4 v = *(const float4*)&x[(size_t)(m0 + row) * DD + k0 + cg];
            As[cg + 0][row] = v.x; As[cg + 1][row] = v.y;
            As[cg + 2][row] = v.z; As[cg + 3][row] = v.w;
        }
        // B tile: W rows k0..k0+15, cols n0..n0+63
        {
            int kk = tid >> 4;
            int c  = (tid & 15) * 4;
            int n  = n0 + c;
            float4 v;
            if (n < 512) v = *(const float4*)&Wq[(size_t)(k0 + kk) * 512 + n];
            else         v = *(const float4*)&Wkv[(size_t)(k0 + kk) * 1024 + (n - 512)];
            Bs[kk][c + 0] = v.x; Bs[kk][c + 1] = v.y;
            Bs[kk][c + 2] = v.z; Bs[kk][c + 3] = v.w;
        }
        __syncthreads();
        #pragma unroll
        for (int kk = 0; kk < 16; kk++) {
            float a[4], b[4];
            #pragma unroll
            for (int i = 0; i < 4; i++) a[i] = As[kk][ty * 4 + i];
            #pragma unroll
            for (int j = 0; j < 4; j++) b[j] = Bs[kk][tx * 4 + j];
            #pragma unroll
            for (int i = 0; i < 4; i++)
                #pragma unroll
                for (int j = 0; j < 4; j++) acc[i][j] += a[i] * b[j];
        }
        __syncthreads();
    }

    #pragma unroll
    for (int i = 0; i < 4; i++) {
        int m = m0 + ty * 4 + i;
        int b = m >> 10, s = m & 1023;
        #pragma unroll
        for (int j = 0; j < 4; j++) {
            int n = n0 + tx * 4 + j;
            float val = acc[i][j];
            float* dst; int hcol;
            if (n < 512)        { dst = g_q; hcol = n;        val *= 0.125f; }
            else if (n < 1024)  { dst = g_k; hcol = n - 512;  }
            else                { dst = g_v; hcol = n - 1024; }
            int h = hcol >> 6, d = hcol & 63;
            dst[(((size_t)(b * HH + h) << 10) + s) * HD + d] = val;
        }
    }
}

// ============================================================================
// Kernel 2: QP = q @ pemb^T.  M=32768 ((b,h,s) flat), N=1025, K=64.
// q already scaled by 0.125.
// ============================================================================
__global__ __launch_bounds__(256) void qp_gemm(const float* __restrict__ pemb) {
    __shared__ float As[16][68];
    __shared__ float Bs[16][68];
    const int m0 = blockIdx.y * 64;
    const int n0 = blockIdx.x * 64;
    const int tid = threadIdx.x;
    const int ty = tid >> 4, tx = tid & 15;

    float acc[4][4] = {};

    for (int k0 = 0; k0 < HD; k0 += 16) {
        {
            int row = tid >> 2;
            int cg  = (tid & 3) * 4;
            float4 v = *(const float4*)&g_q[(size_t)(m0 + row) * HD + k0 + cg];
            As[cg + 0][row] = v.x; As[cg + 1][row] = v.y;
            As[cg + 2][row] = v.z; As[cg + 3][row] = v.w;
        }
        {
            // B(k,n) = pemb[n*64 + k]; load pemb row-major, store transposed
            int nl = tid >> 2;           // 0..63
            int kg = (tid & 3) * 4;      // 0,4,8,12
            int n  = n0 + nl;
            float4 v = make_float4(0.f, 0.f, 0.f, 0.f);
            if (n < NP) v = *(const float4*)&pemb[(size_t)n * HD + k0 + kg];
            Bs[kg + 0][nl] = v.x; Bs[kg + 1][nl] = v.y;
            Bs[kg + 2][nl] = v.z; Bs[kg + 3][nl] = v.w;
        }
        __syncthreads();
        #pragma unroll
        for (int kk = 0; kk < 16; kk++) {
            float a[4], b[4];
            #pragma unroll
            for (int i = 0; i < 4; i++) a[i] = As[kk][ty * 4 + i];
            #pragma unroll
            for (int j = 0; j < 4; j++) b[j] = Bs[kk][tx * 4 + j];
            #pragma unroll
            for (int i = 0; i < 4; i++)
                #pragma unroll
                for (int j = 0; j < 4; j++) acc[i][j] += a[i] * b[j];
        }
        __syncthreads();
    }

    #pragma unroll
    for (int i = 0; i < 4; i++) {
        int m = m0 + ty * 4 + i;
        #pragma unroll
        for (int j = 0; j < 4; j++) {
            int n = n0 + tx * 4 + j;
            if (n < NP) g_qp[(size_t)m * NP + n] = acc[i][j];
        }
    }
}

// ============================================================================
// Kernel 3: flash-style attention with positional gather.
// Block = 256 threads. Query tile 64, key tile 32, hd=64.
// Per-row softmax state replicated across the 16-lane tx group.
// ============================================================================
__global__ __launch_bounds__(256) void attn_kernel() {
    const int bh = blockIdx.y;            // 0..31  (b*8+h)
    const int q0 = blockIdx.x * 64;       // query tile start
    const int tid = threadIdx.x;
    const int ty = tid >> 4, tx = tid & 15;

    __shared__ float sQ[64][65];
    __shared__ float sK[32][65];
    __shared__ float sV[32][65];
    __shared__ float sP[64][33];

    // load Q tile [64][64]
    #pragma unroll
    for (int it = 0; it < 4; it++) {
        int row = it * 16 + (tid >> 4);
        int cg  = (tid & 15) * 4;
        float4 v = *(const float4*)&g_q[((size_t)bh * SS + q0 + row) * HD + cg];
        sQ[row][cg + 0] = v.x; sQ[row][cg + 1] = v.y;
        sQ[row][cg + 2] = v.z; sQ[row][cg + 3] = v.w;
    }

    float o[4][4] = {};
    float rmax[4], rsum[4];
    #pragma unroll
    for (int i = 0; i < 4; i++) { rmax[i] = -1e30f; rsum[i] = 0.f; }

    for (int kt = 0; kt < SS / 32; kt++) {
        const int t0 = kt * 32;
        // load K,V tiles [32][64]
        #pragma unroll
        for (int it = 0; it < 2; it++) {
            int row = it * 16 + (tid >> 4);
            int cg  = (tid & 15) * 4;
            size_t base = ((size_t)bh * SS + t0 + row) * HD + cg;
            float4 kv = *(const float4*)&g_k[base];
            sK[row][cg + 0] = kv.x; sK[row][cg + 1] = kv.y;
            sK[row][cg + 2] = kv.z; sK[row][cg + 3] = kv.w;
            float4 vv = *(const float4*)&g_v[base];
            sV[row][cg + 0] = vv.x; sV[row][cg + 1] = vv.y;
            sV[row][cg + 2] = vv.z; sV[row][cg + 3] = vv.w;
        }
        __syncthreads();

        // S tile 64x32: each thread 4 rows x 2 cols
        float sc[4][2] = {};
        #pragma unroll
        for (int d = 0; d < 64; d++) {
            float a[4], b[2];
            #pragma unroll
            for (int i = 0; i < 4; i++) a[i] = sQ[ty * 4 + i][d];
            #pragma unroll
            for (int j = 0; j < 2; j++) b[j] = sK[tx * 2 + j][d];
            #pragma unroll
            for (int i = 0; i < 4; i++)
                #pragma unroll
                for (int j = 0; j < 2; j++) sc[i][j] += a[i] * b[j];
        }
        // add positional bias (gather from qp; already scaled)
        #pragma unroll
        for (int i = 0; i < 4; i++) {
            int s_g = q0 + ty * 4 + i;
            size_t rowbase = ((size_t)bh * SS + s_g) * NP;
            #pragma unroll
            for (int j = 0; j < 2; j++) {
                int t = t0 + tx * 2 + j;
                int dlt = s_g - t;
                dlt = min(512, max(-512, dlt));
                sc[i][j] += g_qp[rowbase + dlt + 512];
            }
        }
        // online softmax per row (16-lane groups share a row)
        #pragma unroll
        for (int i = 0; i < 4; i++) {
            float m = fmaxf(sc[i][0], sc[i][1]);
            #pragma unroll
            for (int off = 8; off > 0; off >>= 1)
                m = fmaxf(m, __shfl_xor_sync(0xffffffffu, m, off));
            float newm = fmaxf(rmax[i], m);
            float corr = __expf(rmax[i] - newm);
            rmax[i] = newm;
            float p0 = __expf(sc[i][0] - newm);
            float p1 = __expf(sc[i][1] - newm);
            float lsum = p0 + p1;
            #pragma unroll
            for (int off = 8; off > 0; off >>= 1)
                lsum += __shfl_xor_sync(0xffffffffu, lsum, off);
            rsum[i] = rsum[i] * corr + lsum;
            sP[ty * 4 + i][tx * 2 + 0] = p0;
            sP[ty * 4 + i][tx * 2 + 1] = p1;
            #pragma unroll
            for (int j = 0; j < 4; j++) o[i][j] *= corr;
        }
        __syncthreads();

        // O += P @ V : each thread 4 rows x 4 hd-cols, c over 32 keys
        #pragma unroll
        for (int c = 0; c < 32; c++) {
            float p[4], v[4];
            #pragma unroll
            for (int i = 0; i < 4; i++) p[i] = sP[ty * 4 + i][c];
            #pragma unroll
            for (int j = 0; j < 4; j++) v[j] = sV[c][tx * 4 + j];
            #pragma unroll
            for (int i = 0; i < 4; i++)
                #pragma unroll
                for (int j = 0; j < 4; j++) o[i][j] += p[i] * v[j];
        }
        __syncthreads();
    }

    // write ctx [b, s, h*64+d]
    const int b = bh >> 3, h = bh & 7;
    #pragma unroll
    for (int i = 0; i < 4; i++) {
        int s = q0 + ty * 4 + i;
        float inv = 1.0f / rsum[i];
        #pragma unroll
        for (int j = 0; j < 4; j++) {
            int d = tx * 4 + j;
            g_ctx[((size_t)(b * SS + s) * (HH * HD)) + h * HD + d] = o[i][j] * inv;
        }
    }
}

// ============================================================================
// Kernel 4: output projection.  out = ctx @ Wout + bout.  M=4096,N=512,K=512.
// ============================================================================
__global__ __launch_bounds__(256) void out_gemm(const float* __restrict__ Wout,
                                                const float* __restrict__ bout,
                                                float* __restrict__ out) {
    __shared__ float As[16][68];
    __shared__ float Bs[16][68];
    const int m0 = blockIdx.y * 64;
    const int n0 = blockIdx.x * 64;
    const int tid = threadIdx.x;
    const int ty = tid >> 4, tx = tid & 15;

    float acc[4][4] = {};

    for (int k0 = 0; k0 < DD; k0 += 16) {
        {
            int row = tid >> 2;
            int cg  = (tid & 3) * 4;
            float4 v = *(const float4*)&g_ctx[(size_t)(m0 + row) * DD + k0 + cg];
            As[cg + 0][row] = v.x; As[cg + 1][row] = v.y;
            As[cg + 2][row] = v.z; As[cg + 3][row] = v.w;
        }
        {
            int kk = tid >> 4;
            int c  = (tid & 15) * 4;
            float4 v = *(const float4*)&Wout[(size_t)(k0 + kk) * DD + n0 + c];
            Bs[kk][c + 0] = v.x; Bs[kk][c + 1] = v.y;
            Bs[kk][c + 2] = v.z; Bs[kk][c + 3] = v.w;
        }
        __syncthreads();
        #pragma unroll
        for (int kk = 0; kk < 16; kk++) {
            float a[4], b[4];
            #pragma unroll
            for (int i = 0; i < 4; i++) a[i] = As[kk][ty * 4 + i];
            #pragma unroll
            for (int j = 0; j < 4; j++) b[j] = Bs[kk][tx * 4 + j];
            #pragma unroll
            for (int i = 0; i < 4; i++)
                #pragma unroll
                for (int j = 0; j < 4; j++) acc[i][j] += a[i] * b[j];
        }
        __syncthreads();
    }

    #pragma unroll
    for (int i = 0; i < 4; i++) {
        int m = m0 + ty * 4 + i;
        #pragma unroll
        for (int j = 0; j < 4; j++) {
            int n = n0 + tx * 4 + j;
            out[(size_t)m * DD + n] = acc[i][j] + bout[n];
        }
    }
}

// ============================================================================
extern "C" void kernel_launch(void* const* d_in, const int* in_sizes, int n_in,
                              void* d_out, int out_size) {
    const float* x    = (const float*)d_in[0];
    // d_in[1] = attn_mask (unused by reference)
    const float* Wq   = (const float*)d_in[2];
    const float* Wkv  = (const float*)d_in[3];
    const float* Wout = (const float*)d_in[4];
    const float* bout = (const float*)d_in[5];
    const float* pemb = (const float*)d_in[6];
    float* out = (float*)d_out;

    // 1) QKV projection (M=4096, N=1536)
    qkv_gemm<<<dim3(1536 / 64, 4096 / 64), 256>>>(x, Wq, Wkv);

    // 2) qp = q @ pemb^T (M=32768, N=1025)
    qp_gemm<<<dim3((NP + 63) / 64, (BB * HH * SS) / 64), 256>>>(pemb);

    // 3) attention (16 q-tiles x 32 (b,h))
    attn_kernel<<<dim3(SS / 64, BB * HH), 256>>>();

    // 4) output projection (M=4096, N=512)
    out_gemm<<<dim3(DD / 64, 4096 / 64), 256>>>(Wout, bout, out);
}

// round 4
// speedup vs baseline: 2.0962x; 2.0961x over previous
#include <cuda_runtime.h>
#include <math.h>
#include <stdint.h>

#define BB 4
#define SS 1024
#define DD 512
#define HH 8
#define HD 64
#define NP 1025   // pemb rows (2*512+1)

// ---------------- scratch (device globals; allocation-free) ----------------
__device__ float g_q[BB*HH*SS*HD];              // [b,h,s,d], pre-scaled by 0.125
__device__ float g_k[BB*HH*SS*HD];
__device__ float g_v[BB*HH*SS*HD];
__device__ float g_qp[(size_t)BB*HH*SS*NP];     // [b,h,s, 1025]
__device__ float g_ctx[BB*SS*HH*HD];            // [b,s, h*64+d]

// ---------------- helpers ----------------
__device__ __forceinline__ uint32_t f2tf32(float f) {
    uint32_t u;
    asm("cvt.rna.tf32.f32 %0, %1;" : "=r"(u) : "f"(f));
    return u;
}

__device__ __forceinline__ void mma_tf32(float* c, const uint32_t* a, const uint32_t* b) {
    asm volatile(
        "mma.sync.aligned.m16n8k8.row.col.f32.tf32.tf32.f32 "
        "{%0,%1,%2,%3},{%4,%5,%6,%7},{%8,%9},{%0,%1,%2,%3};\n"
        : "+f"(c[0]), "+f"(c[1]), "+f"(c[2]), "+f"(c[3])
        : "r"(a[0]), "r"(a[1]), "r"(a[2]), "r"(a[3]),
          "r"(b[0]), "r"(b[1]));
}

// ============================================================================
// Generic tf32 GEMM: C[M,N] = A[M,K] @ B[K,N], BM=128, BN=64, BK=16,
// 256 threads = 8 warps in 4(m) x 2(n); each warp 32x32 = 2 m-tiles x 4 n-tiles.
// MODE 0: QKV projection (A=x, B=Wq|Wkv, scatter epilogue, q *= 0.125)
// MODE 1: QP (A=g_q, B=pemb^T, K=64, N=1025 with guard)
// MODE 2: out proj (A=g_ctx, B=Wout, bias add)
// ============================================================================
template<int MODE>
__global__ __launch_bounds__(256) void gemm_tf32(const float* __restrict__ A,
                                                 const float* __restrict__ B,
                                                 const float* __restrict__ B2,
                                                 const float* __restrict__ bias,
                                                 float* __restrict__ Cout) {
    constexpr int K = (MODE == 1) ? 64 : 512;
    __shared__ uint32_t As[128][20];   // [m][k], stride 20 -> conflict-free a-frag loads
    __shared__ uint32_t Bs[16][72];    // [k][n], stride 72 -> conflict-free b-frag loads

    const int m0 = blockIdx.y * 128;
    const int n0 = blockIdx.x * 64;
    const int tid = threadIdx.x;
    const int lane = tid & 31;
    const int w = tid >> 5;
    const int wm = w & 3;        // 0..3 -> 32-row group
    const int wn = w >> 2;       // 0..1 -> 32-col group
    const int group = lane >> 2; // 0..7
    const int tid4 = lane & 3;   // 0..3

    const float* Aptr = (MODE == 0) ? A : (MODE == 1 ? g_q : g_ctx);

    float c[2][4][4] = {};

    for (int k0 = 0; k0 < K; k0 += 16) {
        // ---- load A tile (128 x 16) ----
        {
            int row = tid >> 1;
            #pragma unroll
            for (int j = 0; j < 2; j++) {
                int cg = (tid & 1) * 8 + j * 4;
                float4 v = *(const float4*)&Aptr[(size_t)(m0 + row) * K + k0 + cg];
                As[row][cg + 0] = f2tf32(v.x);
                As[row][cg + 1] = f2tf32(v.y);
                As[row][cg + 2] = f2tf32(v.z);
                As[row][cg + 3] = f2tf32(v.w);
            }
        }
        // ---- load B tile (16 x 64) ----
        if (MODE == 0) {
            int kk = tid >> 4, cg = (tid & 15) * 4;
            int n = n0 + cg;
            float4 v;
            if (n < 512) v = *(const float4*)&B [(size_t)(k0 + kk) * 512  + n];
            else         v = *(const float4*)&B2[(size_t)(k0 + kk) * 1024 + (n - 512)];
            Bs[kk][cg + 0] = f2tf32(v.x);
            Bs[kk][cg + 1] = f2tf32(v.y);
            Bs[kk][cg + 2] = f2tf32(v.z);
            Bs[kk][cg + 3] = f2tf32(v.w);
        } else if (MODE == 2) {
            int kk = tid >> 4, cg = (tid & 15) * 4;
            float4 v = *(const float4*)&B[(size_t)(k0 + kk) * 512 + n0 + cg];
            Bs[kk][cg + 0] = f2tf32(v.x);
            Bs[kk][cg + 1] = f2tf32(v.y);
            Bs[kk][cg + 2] = f2tf32(v.z);
            Bs[kk][cg + 3] = f2tf32(v.w);
        } else {
            // B(k,n) = pemb[n][k] -> transpose on load
            int nl = tid >> 2, kg = (tid & 3) * 4;
            int n = n0 + nl;
            float4 v = make_float4(0.f, 0.f, 0.f, 0.f);
            if (n < NP) v = *(const float4*)&B[(size_t)n * HD + k0 + kg];
            Bs[kg + 0][nl] = f2tf32(v.x);
            Bs[kg + 1][nl] = f2tf32(v.y);
            Bs[kg + 2][nl] = f2tf32(v.z);
            Bs[kg + 3][nl] = f2tf32(v.w);
        }
        __syncthreads();

        #pragma unroll
        for (int ks = 0; ks < 16; ks += 8) {
            uint32_t a[2][4];
            #pragma unroll
            for (int mt = 0; mt < 2; mt++) {
                int r = wm * 32 + mt * 16;
                a[mt][0] = As[r + group    ][ks + tid4    ];
                a[mt][1] = As[r + group + 8][ks + tid4    ];
                a[mt][2] = As[r + group    ][ks + tid4 + 4];
                a[mt][3] = As[r + group + 8][ks + tid4 + 4];
            }
            #pragma unroll
            for (int nt = 0; nt < 4; nt++) {
                int cidx = wn * 32 + nt * 8 + group;
                uint32_t b[2];
                b[0] = Bs[ks + tid4    ][cidx];
                b[1] = Bs[ks + tid4 + 4][cidx];
                #pragma unroll
                for (int mt = 0; mt < 2; mt++)
                    mma_tf32(c[mt][nt], a[mt], b);
            }
        }
        __syncthreads();
    }

    // ---- epilogue ----
    #pragma unroll
    for (int mt = 0; mt < 2; mt++) {
        #pragma unroll
        for (int nt = 0; nt < 4; nt++) {
            #pragma unroll
            for (int e = 0; e < 4; e++) {
                int row = m0 + wm * 32 + mt * 16 + group + ((e >> 1) * 8);
                int col = n0 + wn * 32 + nt * 8 + 2 * tid4 + (e & 1);
                float val = c[mt][nt][e];
                if (MODE == 0) {
                    int b = row >> 10, s = row & 1023;
                    float* dst; int hcol;
                    if (col < 512)       { dst = g_q; hcol = col;        val *= 0.125f; }
                    else if (col < 1024) { dst = g_k; hcol = col - 512;  }
                    else                 { dst = g_v; hcol = col - 1024; }
                    int h = hcol >> 6, d = hcol & 63;
                    dst[(((size_t)(b * HH + h) << 10) + s) * HD + d] = val;
                } else if (MODE == 1) {
                    if (col < NP) g_qp[(size_t)row * NP + col] = val;
                } else {
                    Cout[(size_t)row * DD + col] = val + bias[col];
                }
            }
        }
    }
}

// ============================================================================
// Flash attention on tf32 mma: q-tile 64, k-tile 32, 256 threads = 8 warps
// in 4(row) x 2(col). Positional bias gathered from g_qp per C element.
// ============================================================================
__global__ __launch_bounds__(256) void attn_mma() {
    const int bh = blockIdx.y;
    const int q0 = blockIdx.x * 64;
    const int tid = threadIdx.x;
    const int lane = tid & 31;
    const int w = tid >> 5;
    const int wm = w & 3;        // 16-row group within q tile
    const int wn = w >> 2;       // 0/1: 16-col group for S, 32-col group for O
    const int group = lane >> 2;
    const int tid4 = lane & 3;

    __shared__ uint32_t sQ[64][68];
    __shared__ uint32_t sK[32][68];
    __shared__ uint32_t sV[32][72];
    __shared__ uint32_t sP[64][36];
    __shared__ float redM[2][64];
    __shared__ float redS[2][64];

    // load Q tile (tf32)
    #pragma unroll
    for (int j = 0; j < 4; j++) {
        int idx = tid + j * 256;
        int row = idx >> 4, cg = (idx & 15) * 4;
        float4 v = *(const float4*)&g_q[((size_t)bh * SS + q0 + row) * HD + cg];
        sQ[row][cg + 0] = f2tf32(v.x);
        sQ[row][cg + 1] = f2tf32(v.y);
        sQ[row][cg + 2] = f2tf32(v.z);
        sQ[row][cg + 3] = f2tf32(v.w);
    }

    float cO[4][4] = {};
    float rmax0 = -1e30f, rmax1 = -1e30f;
    float rsum0 = 0.f, rsum1 = 0.f;
    const int row0 = wm * 16 + group;       // local row of c0/c1
    const int row1 = row0 + 8;              // local row of c2/c3
    const size_t qpb0 = ((size_t)bh * SS + q0 + row0) * NP + 512;
    const size_t qpb1 = ((size_t)bh * SS + q0 + row1) * NP + 512;

    for (int kt = 0; kt < SS / 32; kt++) {
        const int t0 = kt * 32;
        // load K,V tiles (32x64)
        #pragma unroll
        for (int j = 0; j < 2; j++) {
            int idx = tid + j * 256;
            int row = idx >> 4, cg = (idx & 15) * 4;
            size_t base = ((size_t)bh * SS + t0 + row) * HD + cg;
            float4 kv = *(const float4*)&g_k[base];
            sK[row][cg + 0] = f2tf32(kv.x);
            sK[row][cg + 1] = f2tf32(kv.y);
            sK[row][cg + 2] = f2tf32(kv.z);
            sK[row][cg + 3] = f2tf32(kv.w);
            float4 vv = *(const float4*)&g_v[base];
            sV[row][cg + 0] = f2tf32(vv.x);
            sV[row][cg + 1] = f2tf32(vv.y);
            sV[row][cg + 2] = f2tf32(vv.z);
            sV[row][cg + 3] = f2tf32(vv.w);
        }
        __syncthreads();

        // ---- S = Q @ K^T (16 rows x 16 cols per warp) ----
        float cS[2][4] = {};
        #pragma unroll
        for (int ks = 0; ks < 8; ks++) {
            uint32_t a[4];
            a[0] = sQ[row0][ks * 8 + tid4    ];
            a[1] = sQ[row1][ks * 8 + tid4    ];
            a[2] = sQ[row0][ks * 8 + tid4 + 4];
            a[3] = sQ[row1][ks * 8 + tid4 + 4];
            #pragma unroll
            for (int nt = 0; nt < 2; nt++) {
                int kc = wn * 16 + nt * 8 + group;
                uint32_t b[2];
                b[0] = sK[kc][ks * 8 + tid4    ];
                b[1] = sK[kc][ks * 8 + tid4 + 4];
                mma_tf32(cS[nt], a, b);
            }
        }

        // ---- positional bias + per-warp row max ----
        float mloc0 = -1e30f, mloc1 = -1e30f;
        const int s0 = q0 + row0, s1 = q0 + row1;
        #pragma unroll
        for (int nt = 0; nt < 2; nt++) {
            #pragma unroll
            for (int e = 0; e < 4; e++) {
                int t = t0 + wn * 16 + nt * 8 + 2 * tid4 + (e & 1);
                int s_g = (e < 2) ? s0 : s1;
                int dlt = s_g - t;
                dlt = min(512, max(-512, dlt));
                float v = cS[nt][e] + g_qp[((e < 2) ? qpb0 : qpb1) + dlt];
                cS[nt][e] = v;
                if (e < 2) mloc0 = fmaxf(mloc0, v);
                else       mloc1 = fmaxf(mloc1, v);
            }
        }
        mloc0 = fmaxf(mloc0, __shfl_xor_sync(0xffffffffu, mloc0, 1));
        mloc0 = fmaxf(mloc0, __shfl_xor_sync(0xffffffffu, mloc0, 2));
        mloc1 = fmaxf(mloc1, __shfl_xor_sync(0xffffffffu, mloc1, 1));
        mloc1 = fmaxf(mloc1, __shfl_xor_sync(0xffffffffu, mloc1, 2));
        if (tid4 == 0) { redM[wn][row0] = mloc0; redM[wn][row1] = mloc1; }
        __syncthreads();

        float mnew0 = fmaxf(rmax0, fmaxf(redM[0][row0], redM[1][row0]));
        float mnew1 = fmaxf(rmax1, fmaxf(redM[0][row1], redM[1][row1]));
        float corr0 = __expf(rmax0 - mnew0);
        float corr1 = __expf(rmax1 - mnew1);
        rmax0 = mnew0; rmax1 = mnew1;

        float ls0 = 0.f, ls1 = 0.f;
        #pragma unroll
        for (int nt = 0; nt < 2; nt++) {
            #pragma unroll
            for (int e = 0; e < 4; e++) {
                float p = __expf(cS[nt][e] - ((e < 2) ? mnew0 : mnew1));
                if (e < 2) ls0 += p; else ls1 += p;
                int r = (e < 2) ? row0 : row1;
                sP[r][wn * 16 + nt * 8 + 2 * tid4 + (e & 1)] = f2tf32(p);
            }
        }
        ls0 += __shfl_xor_sync(0xffffffffu, ls0, 1);
        ls0 += __shfl_xor_sync(0xffffffffu, ls0, 2);
        ls1 += __shfl_xor_sync(0xffffffffu, ls1, 1);
        ls1 += __shfl_xor_sync(0xffffffffu, ls1, 2);
        if (tid4 == 0) { redS[wn][row0] = ls0; redS[wn][row1] = ls1; }
        __syncthreads();

        rsum0 = rsum0 * corr0 + redS[0][row0] + redS[1][row0];
        rsum1 = rsum1 * corr1 + redS[0][row1] + redS[1][row1];

        #pragma unroll
        for (int nt2 = 0; nt2 < 4; nt2++) {
            cO[nt2][0] *= corr0; cO[nt2][1] *= corr0;
            cO[nt2][2] *= corr1; cO[nt2][3] *= corr1;
        }

        // ---- O += P @ V (16 rows x 32 hd-cols per warp) ----
        #pragma unroll
        for (int ks = 0; ks < 4; ks++) {
            uint32_t a[4];
            a[0] = sP[row0][ks * 8 + tid4    ];
            a[1] = sP[row1][ks * 8 + tid4    ];
            a[2] = sP[row0][ks * 8 + tid4 + 4];
            a[3] = sP[row1][ks * 8 + tid4 + 4];
            #pragma unroll
            for (int nt2 = 0; nt2 < 4; nt2++) {
                int dc = wn * 32 + nt2 * 8 + group;
                uint32_t b[2];
                b[0] = sV[ks * 8 + tid4    ][dc];
                b[1] = sV[ks * 8 + tid4 + 4][dc];
                mma_tf32(cO[nt2], a, b);
            }
        }
        __syncthreads();
    }

    // ---- write ctx [b, s, h*64+d] ----
    const int b = bh >> 3, h = bh & 7;
    const float inv0 = 1.0f / rsum0, inv1 = 1.0f / rsum1;
    #pragma unroll
    for (int nt2 = 0; nt2 < 4; nt2++) {
        #pragma unroll
        for (int e = 0; e < 4; e++) {
            int d = wn * 32 + nt2 * 8 + 2 * tid4 + (e & 1);
            int s = q0 + ((e < 2) ? row0 : row1);
            float val = cO[nt2][e] * ((e < 2) ? inv0 : inv1);
            g_ctx[((size_t)(b * SS + s)) * (HH * HD) + h * HD + d] = val;
        }
    }
}

// ============================================================================
extern "C" void kernel_launch(void* const* d_in, const int* in_sizes, int n_in,
                              void* d_out, int out_size) {
    const float* x    = (const float*)d_in[0];
    // d_in[1] = attn_mask (unused by reference)
    const float* Wq   = (const float*)d_in[2];
    const float* Wkv  = (const float*)d_in[3];
    const float* Wout = (const float*)d_in[4];
    const float* bout = (const float*)d_in[5];
    const float* pemb = (const float*)d_in[6];
    float* out = (float*)d_out;

    // 1) QKV projection: M=4096, N=1536, K=512
    gemm_tf32<0><<<dim3(1536 / 64, 4096 / 128), 256>>>(x, Wq, Wkv, nullptr, nullptr);

    // 2) qp = q @ pemb^T: M=32768, N=1025, K=64
    gemm_tf32<1><<<dim3((NP + 63) / 64, (BB * HH * SS) / 128), 256>>>(nullptr, pemb, nullptr, nullptr, nullptr);

    // 3) attention: 16 q-tiles x 32 (b,h)
    attn_mma<<<dim3(SS / 64, BB * HH), 256>>>();

    // 4) out projection: M=4096, N=512, K=512
    gemm_tf32<2><<<dim3(DD / 64, 4096 / 128), 256>>>(nullptr, Wout, nullptr, bout, out);
}